// round 13
// baseline (speedup 1.0000x reference)
#include <cuda_runtime.h>

#define N_CLASS   10
#define PSTRIDE   12
#define MAX_NODES 100000

typedef unsigned long long ull;

__device__ __align__(16) float g_P[MAX_NODES * PSTRIDE];
__device__ __align__(16) float g_Q[MAX_NODES * PSTRIDE];

// packed fp32x2 ops
#define FFMA2(acc, a, b) \
    asm("fma.rn.f32x2 %0, %1, %2, %0;" : "+l"(acc) : "l"(a), "l"(b))
#define FADD2(r, a, b) \
    asm("add.rn.f32x2 %0, %1, %2;" : "=l"(r) : "l"(a), "l"(b))

__device__ __forceinline__ ull pack2(float x, float y) {
    ull r;
    asm("mov.b64 %0, {%1, %2};" : "=l"(r) : "f"(x), "f"(y));
    return r;
}

// lane-resident weights: wp[p][k] = (W[2p][col], W[2p+1][col]) for this lane's 4 cols
__device__ __forceinline__ void load_weights(const float* __restrict__ W, int wcol,
                                             int lane, ull wp[5][4]) {
#pragma unroll
    for (int p = 0; p < 5; p++) {
        float4 wa = ((const float4*)(W + (2 * p) * 384 + wcol))[lane];
        float4 wb = ((const float4*)(W + (2 * p + 1) * 384 + wcol))[lane];
        wp[p][0] = pack2(wa.x, wb.x);
        wp[p][1] = pack2(wa.y, wb.y);
        wp[p][2] = pack2(wa.z, wb.z);
        wp[p][3] = pack2(wa.w, wb.w);
    }
}

__device__ __forceinline__ void dot10(const ull wp[5][4], float4 v, ull acc[5]) {
    ull a0 = pack2(v.x, v.x);
    ull a1 = pack2(v.y, v.y);
    ull a2 = pack2(v.z, v.z);
    ull a3 = pack2(v.w, v.w);
#pragma unroll
    for (int p = 0; p < 5; p++) {
        FFMA2(acc[p], a0, wp[p][0]);
        FFMA2(acc[p], a1, wp[p][1]);
        FFMA2(acc[p], a2, wp[p][2]);
        FFMA2(acc[p], a3, wp[p][3]);
    }
}

// Slot-ordered warp reduction, fully packed, zero selects.
// Slot A holds edge k=perm[octet]; B=k^1; C=k^2; D=k^3. After this, every
// lane of octet o holds the full 10-class result (5 packed pairs) of edge
// perm[o], perm = {0,2,1,3}.
__device__ __forceinline__ void reduce_slots(const ull aA[5], const ull aB[5],
                                             const ull aC[5], const ull aD[5],
                                             ull u[5]) {
#pragma unroll
    for (int q = 0; q < 5; q++) {
        ull tA, tB, w;
        FADD2(tA, aA[q], __shfl_xor_sync(0xffffffffu, aB[q], 16));
        FADD2(tB, aC[q], __shfl_xor_sync(0xffffffffu, aD[q], 16));
        FADD2(w, tA, __shfl_xor_sync(0xffffffffu, tB, 8));
        FADD2(w, w, __shfl_xor_sync(0xffffffffu, w, 4));
        FADD2(w, w, __shfl_xor_sync(0xffffffffu, w, 2));
        FADD2(w, w, __shfl_xor_sync(0xffffffffu, w, 1));
        u[q] = w;
    }
}

// ---------------------------------------------------------------------------
// Fused node projection: first half of grid writes g_P (h@W1^T + b),
// second half writes g_Q (h@W2^T). Pipelined, packed epilogue.
// ---------------------------------------------------------------------------
__global__ __launch_bounds__(128)
void proj_kernel(const float* __restrict__ X, const float* __restrict__ W,
                 const float* __restrict__ bias, int n_rows) {
    int half = gridDim.x >> 1;
    int which = blockIdx.x >= half;
    int bx = which ? (blockIdx.x - half) : blockIdx.x;
    float* outbuf = which ? g_Q : g_P;
    int wcol = which ? 128 : 0;

    int lane = threadIdx.x & 31;
    int warp = (bx * blockDim.x + threadIdx.x) >> 5;
    int nwarps = (half * blockDim.x) >> 5;
    int o = lane >> 3, j = lane & 7;
    int k = ((o & 1) << 1) | (o >> 1);
    int kB = k ^ 1, kC = k ^ 2, kD = k ^ 3;
    int stride = nwarps * 4;

    ull wp[5][4];
    load_weights(W, wcol, lane, wp);

    ull bp0 = 0ull, bp1 = 0ull;
    if (!which && j < 3) {
        if (j < 2) {
            bp0 = pack2(__ldg(bias + 4 * j), __ldg(bias + 4 * j + 1));
            bp1 = pack2(__ldg(bias + 4 * j + 2), __ldg(bias + 4 * j + 3));
        } else {
            bp0 = pack2(__ldg(bias + 8), __ldg(bias + 9));
        }
    }

    const float4* Xv = (const float4*)X;
    int nm1 = n_rows - 1;
    int base = warp * 4;
    if (base >= n_rows) return;

    float4 vA = Xv[(size_t)min(base + k, nm1) * 32 + lane];
    float4 vB = Xv[(size_t)min(base + kB, nm1) * 32 + lane];
    float4 vC = Xv[(size_t)min(base + kC, nm1) * 32 + lane];
    float4 vD = Xv[(size_t)min(base + kD, nm1) * 32 + lane];

    while (true) {
        int nb = base + stride;
        bool has_next = nb < n_rows;
        float4 nA, nB, nC, nD;
        if (has_next) {
            nA = Xv[(size_t)min(nb + k, nm1) * 32 + lane];
            nB = Xv[(size_t)min(nb + kB, nm1) * 32 + lane];
            nC = Xv[(size_t)min(nb + kC, nm1) * 32 + lane];
            nD = Xv[(size_t)min(nb + kD, nm1) * 32 + lane];
        }

        ull aA[5], aB[5], aC[5], aD[5];
#pragma unroll
        for (int q = 0; q < 5; q++) { aA[q] = aB[q] = aC[q] = aD[q] = 0ull; }
        dot10(wp, vA, aA);
        dot10(wp, vB, aB);
        dot10(wp, vC, aC);
        dot10(wp, vD, aD);

        ull u[5];
        reduce_slots(aA, aB, aC, aD, u);

        int ridx = base + k;
        if (ridx < n_rows && j < 3) {
            ull* O = (ull*)(outbuf + (size_t)ridx * PSTRIDE);
            if (j == 0) {
                ull r0, r1;
                FADD2(r0, u[0], bp0);
                FADD2(r1, u[1], bp1);
                O[0] = r0; O[1] = r1;
            } else if (j == 1) {
                ull r0, r1;
                FADD2(r0, u[2], bp0);
                FADD2(r1, u[3], bp1);
                O[2] = r0; O[3] = r1;
            } else {
                ull r0;
                FADD2(r0, u[4], bp0);
                O[4] = r0;
            }
        }

        if (!has_next) break;
        base = nb;
        vA = nA; vB = nB; vC = nC; vD = nD;
    }
}

// ---------------------------------------------------------------------------
// Edge kernel: out[e] = eh[e] @ W[:,256:384]^T + P[src[e]] + Q[dst[e]]
// Pipelined; slot-ordered reduction; packed gather/store epilogue split
// across 3 lanes per octet.
// ---------------------------------------------------------------------------
__global__ __launch_bounds__(128)
void edge_score_kernel(const float* __restrict__ eh, const float* __restrict__ W,
                       const int* __restrict__ src, const int* __restrict__ dst,
                       float* __restrict__ out, int n_edges) {
    int lane = threadIdx.x & 31;
    int warp = (blockIdx.x * blockDim.x + threadIdx.x) >> 5;
    int nwarps = (gridDim.x * blockDim.x) >> 5;
    int o = lane >> 3, j = lane & 7;
    int k = ((o & 1) << 1) | (o >> 1);
    int kB = k ^ 1, kC = k ^ 2, kD = k ^ 3;
    int stride = nwarps * 4;

    ull wp[5][4];
    load_weights(W, 256, lane, wp);

    const float4* Ev = (const float4*)eh;
    int nm1 = n_edges - 1;
    int base = warp * 4;
    if (base >= n_edges) return;

    float4 vA = Ev[(size_t)min(base + k, nm1) * 32 + lane];
    float4 vB = Ev[(size_t)min(base + kB, nm1) * 32 + lane];
    float4 vC = Ev[(size_t)min(base + kC, nm1) * 32 + lane];
    float4 vD = Ev[(size_t)min(base + kD, nm1) * 32 + lane];
    int ce = min(base + k, nm1);
    int s = src[ce], d = dst[ce];            // broadcast within octet

    while (true) {
        int nb = base + stride;
        bool has_next = nb < n_edges;
        float4 nA, nB, nC, nD;
        int ns = 0, nd2 = 0;
        if (has_next) {
            nA = Ev[(size_t)min(nb + k, nm1) * 32 + lane];
            nB = Ev[(size_t)min(nb + kB, nm1) * 32 + lane];
            nC = Ev[(size_t)min(nb + kC, nm1) * 32 + lane];
            nD = Ev[(size_t)min(nb + kD, nm1) * 32 + lane];
            int ne = min(nb + k, nm1);
            ns = src[ne]; nd2 = dst[ne];
        }

        ull aA[5], aB[5], aC[5], aD[5];
#pragma unroll
        for (int q = 0; q < 5; q++) { aA[q] = aB[q] = aC[q] = aD[q] = 0ull; }
        dot10(wp, vA, aA);
        dot10(wp, vB, aB);
        dot10(wp, vC, aC);
        dot10(wp, vD, aD);

        ull u[5];
        reduce_slots(aA, aB, aC, aD, u);

        int eidx = base + k;
        if (eidx < n_edges && j < 3) {
            const float* Pb = g_P + (size_t)s * PSTRIDE;
            const float* Qb = g_Q + (size_t)d * PSTRIDE;
            ull* ob = (ull*)(out + (size_t)eidx * N_CLASS);
            if (j == 0) {
                ulonglong2 P = *(const ulonglong2*)Pb;
                ulonglong2 Q = *(const ulonglong2*)Qb;
                ull r0, r1;
                FADD2(r0, u[0], P.x); FADD2(r0, r0, Q.x);
                FADD2(r1, u[1], P.y); FADD2(r1, r1, Q.y);
                ob[0] = r0; ob[1] = r1;
            } else if (j == 1) {
                ulonglong2 P = *(const ulonglong2*)(Pb + 4);
                ulonglong2 Q = *(const ulonglong2*)(Qb + 4);
                ull r0, r1;
                FADD2(r0, u[2], P.x); FADD2(r0, r0, Q.x);
                FADD2(r1, u[3], P.y); FADD2(r1, r1, Q.y);
                ob[2] = r0; ob[3] = r1;
            } else {
                ull P4 = *(const ull*)(Pb + 8);
                ull Q4 = *(const ull*)(Qb + 8);
                ull r0;
                FADD2(r0, u[4], P4); FADD2(r0, r0, Q4);
                ob[4] = r0;
            }
        }

        if (!has_next) break;
        base = nb;
        vA = nA; vB = nB; vC = nC; vD = nD;
        s = ns; d = nd2;
    }
}

// ---------------------------------------------------------------------------
extern "C" void kernel_launch(void* const* d_in, const int* in_sizes, int n_in,
                              void* d_out, int out_size) {
    const float* h   = (const float*)d_in[0];
    const float* eh  = (const float*)d_in[1];
    const float* W   = (const float*)d_in[2];
    const float* b   = (const float*)d_in[3];
    const int*   src = (const int*)d_in[4];
    const int*   dst = (const int*)d_in[5];
    float*       out = (float*)d_out;

    int n_nodes = in_sizes[0] / 128;
    int n_edges = in_sizes[4];

    proj_kernel<<<1184, 128>>>(h, W, b, n_nodes);          // halves: g_P | g_Q
    edge_score_kernel<<<1184, 128>>>(eh, W, src, dst, out, n_edges);
}

// round 14
// speedup vs baseline: 1.4291x; 1.4291x over previous
#include <cuda_runtime.h>

#define N_CLASS   10
#define PSTRIDE   12
#define MAX_NODES 100000

__device__ __align__(16) float g_P[MAX_NODES * PSTRIDE];
__device__ __align__(16) float g_Q[MAX_NODES * PSTRIDE];

// packed fp32x2 fma: acc += a * b
#define FFMA2(acc, a, b) \
    asm("fma.rn.f32x2 %0, %1, %2, %0;" : "+l"(acc) : "l"(a), "l"(b))

__device__ __forceinline__ unsigned long long pack2(float x, float y) {
    unsigned long long r;
    asm("mov.b64 %0, {%1, %2};" : "=l"(r) : "f"(x), "f"(y));
    return r;
}
__device__ __forceinline__ float2 unpack2(unsigned long long p) {
    float2 f;
    asm("mov.b64 {%0, %1}, %2;" : "=f"(f.x), "=f"(f.y) : "l"(p));
    return f;
}

// lane-resident weights: wp[p][k] = (W[2p][col], W[2p+1][col]) for this lane's 4 cols
__device__ __forceinline__ void load_weights(const float* __restrict__ W, int wcol,
                                             int lane, unsigned long long wp[5][4]) {
#pragma unroll
    for (int p = 0; p < 5; p++) {
        float4 wa = ((const float4*)(W + (2 * p) * 384 + wcol))[lane];
        float4 wb = ((const float4*)(W + (2 * p + 1) * 384 + wcol))[lane];
        wp[p][0] = pack2(wa.x, wb.x);
        wp[p][1] = pack2(wa.y, wb.y);
        wp[p][2] = pack2(wa.z, wb.z);
        wp[p][3] = pack2(wa.w, wb.w);
    }
}

__device__ __forceinline__ void dot10(const unsigned long long wp[5][4], float4 v,
                                      unsigned long long acc[5]) {
    unsigned long long a0 = pack2(v.x, v.x);
    unsigned long long a1 = pack2(v.y, v.y);
    unsigned long long a2 = pack2(v.z, v.z);
    unsigned long long a3 = pack2(v.w, v.w);
#pragma unroll
    for (int p = 0; p < 5; p++) {
        FFMA2(acc[p], a0, wp[p][0]);
        FFMA2(acc[p], a1, wp[p][1]);
        FFMA2(acc[p], a2, wp[p][2]);
        FFMA2(acc[p], a3, wp[p][3]);
    }
}

// Reduce 4 rows x 10 classes across the warp (R10 proven version: shallow
// 32-bit shuffle chains, high ILP). After this, every lane of octet o holds
// the full 10-class result of row perm[o], perm = {0,2,1,3}.
__device__ __forceinline__ void reduce4x10(unsigned long long acc[4][5],
                                           float u[N_CLASS], int lane) {
    float p[4][N_CLASS];
#pragma unroll
    for (int g = 0; g < 4; g++)
#pragma unroll
        for (int q = 0; q < 5; q++) {
            float2 f = unpack2(acc[g][q]);
            p[g][2 * q] = f.x;
            p[g][2 * q + 1] = f.y;
        }

    bool lo16 = (lane & 16) == 0;
    float t0[N_CLASS], t1[N_CLASS];
#pragma unroll
    for (int c = 0; c < N_CLASS; c++) {
        float b0 = lo16 ? p[0][c] : p[1][c];
        float s0 = lo16 ? p[1][c] : p[0][c];
        t0[c] = b0 + __shfl_xor_sync(0xffffffffu, s0, 16);
        float b1 = lo16 ? p[2][c] : p[3][c];
        float s1 = lo16 ? p[3][c] : p[2][c];
        t1[c] = b1 + __shfl_xor_sync(0xffffffffu, s1, 16);
    }
    bool lo8 = (lane & 8) == 0;
#pragma unroll
    for (int c = 0; c < N_CLASS; c++) {
        float bc = lo8 ? t0[c] : t1[c];
        float sc = lo8 ? t1[c] : t0[c];
        float v = bc + __shfl_xor_sync(0xffffffffu, sc, 8);
        v += __shfl_xor_sync(0xffffffffu, v, 4);
        v += __shfl_xor_sync(0xffffffffu, v, 2);
        v += __shfl_xor_sync(0xffffffffu, v, 1);
        u[c] = v;
    }
}

// ---------------------------------------------------------------------------
// Fused node projection: first half of grid writes g_P (h@W1^T + b),
// second half writes g_Q (h@W2^T). R10 body, pipelined.
// ---------------------------------------------------------------------------
__global__ __launch_bounds__(128)
void proj_kernel(const float* __restrict__ X, const float* __restrict__ W,
                 const float* __restrict__ bias, int n_rows) {
    int half = gridDim.x >> 1;
    int which = blockIdx.x >= half;
    int bx = which ? (blockIdx.x - half) : blockIdx.x;
    float* outbuf = which ? g_Q : g_P;
    int wcol = which ? 128 : 0;

    int lane = threadIdx.x & 31;
    int warp = (bx * blockDim.x + threadIdx.x) >> 5;
    int nwarps = (half * blockDim.x) >> 5;
    int o = lane >> 3, j = lane & 7;
    int operm = ((o & 1) << 1) | (o >> 1);     // octet -> row perm {0,2,1,3}
    int stride = nwarps * 4;

    unsigned long long wp[5][4];
    load_weights(W, wcol, lane, wp);

    // per-lane bias slice (j<3 stores classes 4j..4j+3 / 8..9)
    float bb0 = 0.f, bb1 = 0.f, bb2 = 0.f, bb3 = 0.f;
    if (which == 0 && j < 3) {
        bb0 = __ldg(bias + j * 4);
        bb1 = __ldg(bias + j * 4 + 1);
        if (j < 2) { bb2 = __ldg(bias + j * 4 + 2); bb3 = __ldg(bias + j * 4 + 3); }
    }

    const float4* Xv = (const float4*)X;
    int nm1 = n_rows - 1;

    int base = warp * 4;
    if (base >= n_rows) return;

    float4 v0 = Xv[(size_t)base * 32 + lane];
    float4 v1 = Xv[(size_t)min(base + 1, nm1) * 32 + lane];
    float4 v2 = Xv[(size_t)min(base + 2, nm1) * 32 + lane];
    float4 v3 = Xv[(size_t)min(base + 3, nm1) * 32 + lane];

    while (true) {
        int nb = base + stride;
        float4 n0, n1, n2, n3;
        bool has_next = nb < n_rows;
        if (has_next) {
            n0 = Xv[(size_t)nb * 32 + lane];
            n1 = Xv[(size_t)min(nb + 1, nm1) * 32 + lane];
            n2 = Xv[(size_t)min(nb + 2, nm1) * 32 + lane];
            n3 = Xv[(size_t)min(nb + 3, nm1) * 32 + lane];
        }

        unsigned long long acc[4][5];
#pragma unroll
        for (int g = 0; g < 4; g++)
#pragma unroll
            for (int q = 0; q < 5; q++) acc[g][q] = 0ull;
        dot10(wp, v0, acc[0]);
        dot10(wp, v1, acc[1]);
        dot10(wp, v2, acc[2]);
        dot10(wp, v3, acc[3]);

        float u[N_CLASS];
        reduce4x10(acc, u, lane);

        int ridx = base + operm;
        if (ridx < n_rows && j < 3) {
            float4* O = (float4*)(outbuf + (size_t)ridx * PSTRIDE);
            if (j == 0)      O[0] = make_float4(u[0] + bb0, u[1] + bb1, u[2] + bb2, u[3] + bb3);
            else if (j == 1) O[1] = make_float4(u[4] + bb0, u[5] + bb1, u[6] + bb2, u[7] + bb3);
            else             O[2] = make_float4(u[8] + bb0, u[9] + bb1, 0.f, 0.f);
        }

        if (!has_next) break;
        base = nb;
        v0 = n0; v1 = n1; v2 = n2; v3 = n3;
    }
}

// ---------------------------------------------------------------------------
// Edge kernel (R10 proven body): out[e] = eh[e]@W3^T + P[src[e]] + Q[dst[e]]
// Software-pipelined; epilogue gathers/stores split across 3 lanes per octet.
// ---------------------------------------------------------------------------
__global__ __launch_bounds__(128)
void edge_score_kernel(const float* __restrict__ eh, const float* __restrict__ W,
                       const int* __restrict__ src, const int* __restrict__ dst,
                       float* __restrict__ out, int n_edges) {
    int lane = threadIdx.x & 31;
    int warp = (blockIdx.x * blockDim.x + threadIdx.x) >> 5;
    int nwarps = (gridDim.x * blockDim.x) >> 5;
    int o = lane >> 3, j = lane & 7;
    int operm = ((o & 1) << 1) | (o >> 1);     // octet -> edge perm {0,2,1,3}
    int stride = nwarps * 4;

    unsigned long long wp[5][4];
    load_weights(W, 256, lane, wp);

    const float4* Ev = (const float4*)eh;
    int nm1 = n_edges - 1;

    int base = warp * 4;
    if (base >= n_edges) return;

    float4 v0 = Ev[(size_t)base * 32 + lane];
    float4 v1 = Ev[(size_t)min(base + 1, nm1) * 32 + lane];
    float4 v2 = Ev[(size_t)min(base + 2, nm1) * 32 + lane];
    float4 v3 = Ev[(size_t)min(base + 3, nm1) * 32 + lane];
    int ce = min(base + operm, nm1);
    int s = src[ce], d = dst[ce];               // broadcast within octet

    while (true) {
        int nb = base + stride;
        float4 n0, n1, n2, n3;
        int ns = 0, nd = 0;
        bool has_next = nb < n_edges;
        if (has_next) {
            n0 = Ev[(size_t)nb * 32 + lane];
            n1 = Ev[(size_t)min(nb + 1, nm1) * 32 + lane];
            n2 = Ev[(size_t)min(nb + 2, nm1) * 32 + lane];
            n3 = Ev[(size_t)min(nb + 3, nm1) * 32 + lane];
            int ne = min(nb + operm, nm1);
            ns = src[ne]; nd = dst[ne];
        }

        unsigned long long acc[4][5];
#pragma unroll
        for (int g = 0; g < 4; g++)
#pragma unroll
            for (int q = 0; q < 5; q++) acc[g][q] = 0ull;
        dot10(wp, v0, acc[0]);
        dot10(wp, v1, acc[1]);
        dot10(wp, v2, acc[2]);
        dot10(wp, v3, acc[3]);

        float u[N_CLASS];
        reduce4x10(acc, u, lane);

        int eidx = base + operm;
        if (eidx < n_edges && j < 3) {
            float4 p = ((const float4*)(g_P + (size_t)s * PSTRIDE))[j];
            float4 q = ((const float4*)(g_Q + (size_t)d * PSTRIDE))[j];
            float2* o2 = (float2*)(out + (size_t)eidx * N_CLASS);
            if (j == 0) {
                o2[0] = make_float2(u[0] + p.x + q.x, u[1] + p.y + q.y);
                o2[1] = make_float2(u[2] + p.z + q.z, u[3] + p.w + q.w);
            } else if (j == 1) {
                o2[2] = make_float2(u[4] + p.x + q.x, u[5] + p.y + q.y);
                o2[3] = make_float2(u[6] + p.z + q.z, u[7] + p.w + q.w);
            } else {
                o2[4] = make_float2(u[8] + p.x + q.x, u[9] + p.y + q.y);
            }
        }

        if (!has_next) break;
        base = nb;
        v0 = n0; v1 = n1; v2 = n2; v3 = n3;
        s = ns; d = nd;
    }
}

// ---------------------------------------------------------------------------
extern "C" void kernel_launch(void* const* d_in, const int* in_sizes, int n_in,
                              void* d_out, int out_size) {
    const float* h   = (const float*)d_in[0];
    const float* eh  = (const float*)d_in[1];
    const float* W   = (const float*)d_in[2];
    const float* b   = (const float*)d_in[3];
    const int*   src = (const int*)d_in[4];
    const int*   dst = (const int*)d_in[5];
    float*       out = (float*)d_out;

    int n_nodes = in_sizes[0] / 128;
    int n_edges = in_sizes[4];

    proj_kernel<<<1184, 128>>>(h, W, b, n_nodes);          // halves: g_P | g_Q
    edge_score_kernel<<<1184, 128>>>(eh, W, src, dst, out, n_edges);
}

// round 15
// speedup vs baseline: 1.5745x; 1.1017x over previous
#include <cuda_runtime.h>

#define N_CLASS   10
#define PSTRIDE   12
#define MAX_NODES 100000

typedef unsigned long long ull;

__device__ __align__(16) float g_P[MAX_NODES * PSTRIDE];
__device__ __align__(16) float g_Q[MAX_NODES * PSTRIDE];

#define FFMA2(acc, a, b) \
    asm("fma.rn.f32x2 %0, %1, %2, %0;" : "+l"(acc) : "l"(a), "l"(b))
#define FMUL2(r, a, b) \
    asm("mul.rn.f32x2 %0, %1, %2;" : "=l"(r) : "l"(a), "l"(b))

__device__ __forceinline__ ull pack2(float x, float y) {
    ull r;
    asm("mov.b64 %0, {%1, %2};" : "=l"(r) : "f"(x), "f"(y));
    return r;
}
__device__ __forceinline__ float2 unpack2(ull p) {
    float2 f;
    asm("mov.b64 {%0, %1}, %2;" : "=f"(f.x), "=f"(f.y) : "l"(p));
    return f;
}

// lane-resident weights: wp[p][k] = (W[2p][col], W[2p+1][col]) for this lane's 4 cols
__device__ __forceinline__ void load_weights(const float* __restrict__ W, int wcol,
                                             int lane, ull wp[5][4]) {
#pragma unroll
    for (int p = 0; p < 5; p++) {
        float4 wa = ((const float4*)(W + (2 * p) * 384 + wcol))[lane];
        float4 wb = ((const float4*)(W + (2 * p + 1) * 384 + wcol))[lane];
        wp[p][0] = pack2(wa.x, wb.x);
        wp[p][1] = pack2(wa.y, wb.y);
        wp[p][2] = pack2(wa.z, wb.z);
        wp[p][3] = pack2(wa.w, wb.w);
    }
}

// First step uses MUL (no zero-init), rest FMA.
__device__ __forceinline__ void dot10f(const ull wp[5][4], float4 v, ull acc[5]) {
    ull a0 = pack2(v.x, v.x);
    ull a1 = pack2(v.y, v.y);
    ull a2 = pack2(v.z, v.z);
    ull a3 = pack2(v.w, v.w);
#pragma unroll
    for (int p = 0; p < 5; p++) {
        FMUL2(acc[p], a0, wp[p][0]);
        FFMA2(acc[p], a1, wp[p][1]);
        FFMA2(acc[p], a2, wp[p][2]);
        FFMA2(acc[p], a3, wp[p][3]);
    }
}

// Hybrid reduction: slot-ordered (SEL-free) folds on unpacked 32-bit floats
// (10 independent shallow chains). Slots: A=edge k, B=k^1, C=k^2, D=k^3.
// After this, every lane of octet o holds the full 10-class result of edge
// base + k(o), k(o) = ((o&1)<<1)|(o>>1).
__device__ __forceinline__ void reduce_hyb(const ull aA[5], const ull aB[5],
                                           const ull aC[5], const ull aD[5],
                                           float u[N_CLASS]) {
    float pA[N_CLASS], pB[N_CLASS], pC[N_CLASS], pD[N_CLASS];
#pragma unroll
    for (int q = 0; q < 5; q++) {
        float2 f;
        f = unpack2(aA[q]); pA[2 * q] = f.x; pA[2 * q + 1] = f.y;
        f = unpack2(aB[q]); pB[2 * q] = f.x; pB[2 * q + 1] = f.y;
        f = unpack2(aC[q]); pC[2 * q] = f.x; pC[2 * q + 1] = f.y;
        f = unpack2(aD[q]); pD[2 * q] = f.x; pD[2 * q + 1] = f.y;
    }
#pragma unroll
    for (int c = 0; c < N_CLASS; c++) {
        float t  = pA[c] + __shfl_xor_sync(0xffffffffu, pB[c], 16);
        float t2 = pC[c] + __shfl_xor_sync(0xffffffffu, pD[c], 16);
        float w  = t + __shfl_xor_sync(0xffffffffu, t2, 8);
        w += __shfl_xor_sync(0xffffffffu, w, 4);
        w += __shfl_xor_sync(0xffffffffu, w, 2);
        w += __shfl_xor_sync(0xffffffffu, w, 1);
        u[c] = w;
    }
}

// ---------------------------------------------------------------------------
// Fused node projection: first half of grid writes g_P (h@W1^T + b),
// second half writes g_Q (h@W2^T). Pipelined, slot-ordered.
// ---------------------------------------------------------------------------
__global__ __launch_bounds__(128)
void proj_kernel(const float* __restrict__ X, const float* __restrict__ W,
                 const float* __restrict__ bias, int n_rows) {
    int half = gridDim.x >> 1;
    int which = blockIdx.x >= half;
    int bx = which ? (blockIdx.x - half) : blockIdx.x;
    float* outbuf = which ? g_Q : g_P;
    int wcol = which ? 128 : 0;

    int lane = threadIdx.x & 31;
    int warp = (bx * blockDim.x + threadIdx.x) >> 5;
    int nwarps = (half * blockDim.x) >> 5;
    int o = lane >> 3, j = lane & 7;
    int k = ((o & 1) << 1) | (o >> 1);
    int kB = k ^ 1, kC = k ^ 2, kD = k ^ 3;
    int stride = nwarps * 4;

    ull wp[5][4];
    load_weights(W, wcol, lane, wp);

    float bb0 = 0.f, bb1 = 0.f, bb2 = 0.f, bb3 = 0.f;
    if (which == 0 && j < 3) {
        bb0 = __ldg(bias + j * 4);
        bb1 = __ldg(bias + j * 4 + 1);
        if (j < 2) { bb2 = __ldg(bias + j * 4 + 2); bb3 = __ldg(bias + j * 4 + 3); }
    }

    const float4* Xv = (const float4*)X;
    int nm1 = n_rows - 1;
    int base = warp * 4;
    if (base >= n_rows) return;

    float4 vA = Xv[(size_t)min(base + k, nm1) * 32 + lane];
    float4 vB = Xv[(size_t)min(base + kB, nm1) * 32 + lane];
    float4 vC = Xv[(size_t)min(base + kC, nm1) * 32 + lane];
    float4 vD = Xv[(size_t)min(base + kD, nm1) * 32 + lane];

    while (true) {
        int nb = base + stride;
        bool has_next = nb < n_rows;
        float4 nA, nB, nC, nD;
        if (has_next) {
            nA = Xv[(size_t)min(nb + k, nm1) * 32 + lane];
            nB = Xv[(size_t)min(nb + kB, nm1) * 32 + lane];
            nC = Xv[(size_t)min(nb + kC, nm1) * 32 + lane];
            nD = Xv[(size_t)min(nb + kD, nm1) * 32 + lane];
        }

        ull aA[5], aB[5], aC[5], aD[5];
        dot10f(wp, vA, aA);
        dot10f(wp, vB, aB);
        dot10f(wp, vC, aC);
        dot10f(wp, vD, aD);

        float u[N_CLASS];
        reduce_hyb(aA, aB, aC, aD, u);

        int ridx = base + k;
        if (ridx < n_rows && j < 3) {
            float4* O = (float4*)(outbuf + (size_t)ridx * PSTRIDE);
            if (j == 0)      O[0] = make_float4(u[0] + bb0, u[1] + bb1, u[2] + bb2, u[3] + bb3);
            else if (j == 1) O[1] = make_float4(u[4] + bb0, u[5] + bb1, u[6] + bb2, u[7] + bb3);
            else             O[2] = make_float4(u[8] + bb0, u[9] + bb1, 0.f, 0.f);
        }

        if (!has_next) break;
        base = nb;
        vA = nA; vB = nB; vC = nC; vD = nD;
    }
}

// ---------------------------------------------------------------------------
// Edge kernel: out[e] = eh[e] @ W[:,256:384]^T + P[src[e]] + Q[dst[e]]
// Pipelined; slot-ordered loads; hybrid reduction; split epilogue.
// ---------------------------------------------------------------------------
__global__ __launch_bounds__(128)
void edge_score_kernel(const float* __restrict__ eh, const float* __restrict__ W,
                       const int* __restrict__ src, const int* __restrict__ dst,
                       float* __restrict__ out, int n_edges) {
    int lane = threadIdx.x & 31;
    int warp = (blockIdx.x * blockDim.x + threadIdx.x) >> 5;
    int nwarps = (gridDim.x * blockDim.x) >> 5;
    int o = lane >> 3, j = lane & 7;
    int k = ((o & 1) << 1) | (o >> 1);
    int kB = k ^ 1, kC = k ^ 2, kD = k ^ 3;
    int stride = nwarps * 4;

    ull wp[5][4];
    load_weights(W, 256, lane, wp);

    const float4* Ev = (const float4*)eh;
    int nm1 = n_edges - 1;
    int base = warp * 4;
    if (base >= n_edges) return;

    float4 vA = Ev[(size_t)min(base + k, nm1) * 32 + lane];
    float4 vB = Ev[(size_t)min(base + kB, nm1) * 32 + lane];
    float4 vC = Ev[(size_t)min(base + kC, nm1) * 32 + lane];
    float4 vD = Ev[(size_t)min(base + kD, nm1) * 32 + lane];
    int ce = min(base + k, nm1);
    int s = src[ce], d = dst[ce];               // broadcast within octet

    while (true) {
        int nb = base + stride;
        bool has_next = nb < n_edges;
        float4 nA, nB, nC, nD;
        int ns = 0, nd = 0;
        if (has_next) {
            nA = Ev[(size_t)min(nb + k, nm1) * 32 + lane];
            nB = Ev[(size_t)min(nb + kB, nm1) * 32 + lane];
            nC = Ev[(size_t)min(nb + kC, nm1) * 32 + lane];
            nD = Ev[(size_t)min(nb + kD, nm1) * 32 + lane];
            int ne = min(nb + k, nm1);
            ns = src[ne]; nd = dst[ne];
        }

        ull aA[5], aB[5], aC[5], aD[5];
        dot10f(wp, vA, aA);
        dot10f(wp, vB, aB);
        dot10f(wp, vC, aC);
        dot10f(wp, vD, aD);

        float u[N_CLASS];
        reduce_hyb(aA, aB, aC, aD, u);

        int eidx = base + k;
        if (eidx < n_edges && j < 3) {
            float4 p = ((const float4*)(g_P + (size_t)s * PSTRIDE))[j];
            float4 q = ((const float4*)(g_Q + (size_t)d * PSTRIDE))[j];
            float2* o2 = (float2*)(out + (size_t)eidx * N_CLASS);
            if (j == 0) {
                o2[0] = make_float2(u[0] + p.x + q.x, u[1] + p.y + q.y);
                o2[1] = make_float2(u[2] + p.z + q.z, u[3] + p.w + q.w);
            } else if (j == 1) {
                o2[2] = make_float2(u[4] + p.x + q.x, u[5] + p.y + q.y);
                o2[3] = make_float2(u[6] + p.z + q.z, u[7] + p.w + q.w);
            } else {
                o2[4] = make_float2(u[8] + p.x + q.x, u[9] + p.y + q.y);
            }
        }

        if (!has_next) break;
        base = nb;
        vA = nA; vB = nB; vC = nC; vD = nD;
        s = ns; d = nd;
    }
}

// ---------------------------------------------------------------------------
extern "C" void kernel_launch(void* const* d_in, const int* in_sizes, int n_in,
                              void* d_out, int out_size) {
    const float* h   = (const float*)d_in[0];
    const float* eh  = (const float*)d_in[1];
    const float* W   = (const float*)d_in[2];
    const float* b   = (const float*)d_in[3];
    const int*   src = (const int*)d_in[4];
    const int*   dst = (const int*)d_in[5];
    float*       out = (float*)d_out;

    int n_nodes = in_sizes[0] / 128;
    int n_edges = in_sizes[4];

    proj_kernel<<<1184, 128>>>(h, W, b, n_nodes);          // halves: g_P | g_Q
    edge_score_kernel<<<1184, 128>>>(eh, W, src, dst, out, n_edges);
}